// round 15
// baseline (speedup 1.0000x reference)
#include <cuda_runtime.h>
#include <cuda_bf16.h>
#include <math.h>
#include <stdint.h>

// Problem constants
#define BATCH    256
#define SEQ      176
#define TIME_LEN 8
#define JOINTS   22
#define D_IN     128
#define H_NUM    8
#define H_DIM    32
#define D_MODEL  256
#define M_TOTAL  (BATCH * SEQ)   // 45056
#define SCALE    0.17677669529663687f

typedef unsigned long long u64;

// ---- warp MMA helpers (plain sm_80+ PTX; valid on sm_103 non-'a') ----
__device__ __forceinline__ uint32_t smem_u32(const void* p) {
    uint32_t a;
    asm("{ .reg .u64 t; cvta.to.shared.u64 t, %1; cvt.u32.u64 %0, t; }" : "=r"(a) : "l"(p));
    return a;
}
__device__ __forceinline__ void ldsm4(uint32_t& r0, uint32_t& r1, uint32_t& r2, uint32_t& r3,
                                      uint32_t addr) {
    asm volatile("ldmatrix.sync.aligned.m8n8.x4.shared.b16 {%0,%1,%2,%3}, [%4];"
                 : "=r"(r0), "=r"(r1), "=r"(r2), "=r"(r3) : "r"(addr));
}
__device__ __forceinline__ void mma16816(float* c, const uint32_t* a, const uint32_t* b) {
    asm volatile(
        "mma.sync.aligned.m16n8k16.row.col.f32.bf16.bf16.f32 "
        "{%0,%1,%2,%3}, {%4,%5,%6,%7}, {%8,%9}, {%0,%1,%2,%3};"
        : "+f"(c[0]), "+f"(c[1]), "+f"(c[2]), "+f"(c[3])
        : "r"(a[0]), "r"(a[1]), "r"(a[2]), "r"(a[3]), "r"(b[0]), "r"(b[1]));
}

// ---- device scratch ----
__device__ float g_q[(size_t)M_TOTAL * D_MODEL];
__device__ float g_k[(size_t)M_TOTAL * D_MODEL];
__device__ float g_v[(size_t)M_TOTAL * D_MODEL];
__device__ __nv_bfloat16 g_xhi[(size_t)M_TOTAL * D_IN];
__device__ __nv_bfloat16 g_xlo[(size_t)M_TOTAL * D_IN];
__device__ __nv_bfloat16 g_wthi[3 * D_MODEL * D_IN];   // transposed: [mtx][n][k]
__device__ __nv_bfloat16 g_wtlo[3 * D_MODEL * D_IN];

// ---------------------------------------------------------------------------
// Split kernels: fp32 -> bf16 hi/lo
// ---------------------------------------------------------------------------
__global__ __launch_bounds__(256) void split_x_kernel(const float* __restrict__ x)
{
    size_t i = ((size_t)blockIdx.x * 256 + threadIdx.x) * 4;
    float4 v = *(const float4*)(x + i);
    __nv_bfloat16 h0 = __float2bfloat16(v.x), h1 = __float2bfloat16(v.y);
    __nv_bfloat16 h2 = __float2bfloat16(v.z), h3 = __float2bfloat16(v.w);
    __nv_bfloat16 l0 = __float2bfloat16(v.x - __bfloat162float(h0));
    __nv_bfloat16 l1 = __float2bfloat16(v.y - __bfloat162float(h1));
    __nv_bfloat16 l2 = __float2bfloat16(v.z - __bfloat162float(h2));
    __nv_bfloat16 l3 = __float2bfloat16(v.w - __bfloat162float(h3));
    __nv_bfloat162 hA; hA.x = h0; hA.y = h1;
    __nv_bfloat162 hB; hB.x = h2; hB.y = h3;
    __nv_bfloat162 lA; lA.x = l0; lA.y = l1;
    __nv_bfloat162 lB; lB.x = l2; lB.y = l3;
    *(__nv_bfloat162*)(g_xhi + i)     = hA;
    *(__nv_bfloat162*)(g_xhi + i + 2) = hB;
    *(__nv_bfloat162*)(g_xlo + i)     = lA;
    *(__nv_bfloat162*)(g_xlo + i + 2) = lB;
}

// W [k=128][n=256] row-major -> Wt [n=256][k=128], split hi/lo. grid (256,3) x 128
__global__ __launch_bounds__(128) void split_w_kernel(
    const float* __restrict__ Wq, const float* __restrict__ Wk, const float* __restrict__ Wv)
{
    const int n = blockIdx.x;
    const int m = blockIdx.y;
    const int k = threadIdx.x;
    const float* W = (m == 0) ? Wq : (m == 1) ? Wk : Wv;
    float v = W[(size_t)k * D_MODEL + n];
    __nv_bfloat16 h = __float2bfloat16(v);
    __nv_bfloat16 l = __float2bfloat16(v - __bfloat162float(h));
    size_t o = (size_t)m * D_MODEL * D_IN + (size_t)n * D_IN + k;
    g_wthi[o] = h;
    g_wtlo[o] = l;
}

// ---------------------------------------------------------------------------
// QKV projection via warp-level mma.sync (bf16, 2-way split, 3 passes).
// Per CTA: M=128 x N=128 x K=128 fully smem-resident. grid=(352, 6).
// (R10/R11 configuration — best measured.)
// ---------------------------------------------------------------------------
#define ROWB 272                    // bytes per smem row (128 bf16 + 8 pad)
#define SA_HI 0
#define SA_LO (128 * ROWB)
#define SB_HI (2 * 128 * ROWB)
#define SB_LO (3 * 128 * ROWB)
#define SMTOT (4 * 128 * ROWB)      // 139264 B

__global__ __launch_bounds__(256) void qkv_mma_kernel(
    const float* __restrict__ bq, const float* __restrict__ bk, const float* __restrict__ bv)
{
    extern __shared__ char smem[];
    const uint32_t sbase = smem_u32(smem);
    const int tid  = threadIdx.x;
    const int w    = tid >> 5;
    const int lane = tid & 31;
    const int mtx  = blockIdx.y >> 1;
    const int half = blockIdx.y & 1;
    const int row0 = blockIdx.x * 128;

    const float* bias = (mtx == 0) ? bq : (mtx == 1) ? bk : bv;
    float* outp       = (mtx == 0) ? g_q : (mtx == 1) ? g_k : g_v;
    const __nv_bfloat16* wth = g_wthi + (size_t)mtx * D_MODEL * D_IN + (size_t)half * 128 * D_IN;
    const __nv_bfloat16* wtl = g_wtlo + (size_t)mtx * D_MODEL * D_IN + (size_t)half * 128 * D_IN;

    for (int idx = tid; idx < 2048; idx += 256) {
        const int r = idx >> 4;
        const int c = (idx & 15) * 8;
        const uint32_t doff = (uint32_t)r * ROWB + c * 2;
        *(uint4*)(smem + SA_HI + doff) = *(const uint4*)(g_xhi + (size_t)(row0 + r) * D_IN + c);
        *(uint4*)(smem + SA_LO + doff) = *(const uint4*)(g_xlo + (size_t)(row0 + r) * D_IN + c);
        *(uint4*)(smem + SB_HI + doff) = *(const uint4*)(wth + (size_t)r * D_IN + c);
        *(uint4*)(smem + SB_LO + doff) = *(const uint4*)(wtl + (size_t)r * D_IN + c);
    }
    __syncthreads();

    const int wm = w & 1;
    const int wn = w >> 1;

    float acc[4][4][4];
#pragma unroll
    for (int i = 0; i < 4; ++i)
#pragma unroll
        for (int j = 0; j < 4; ++j)
#pragma unroll
            for (int e = 0; e < 4; ++e) acc[i][j][e] = 0.0f;

    const uint32_t a_lane = (uint32_t)(wm * 64 + (lane & 15)) * ROWB + ((lane >> 4) * 8) * 2;
    const uint32_t b_lane = (uint32_t)(wn * 32 + (lane & 7) + ((lane >> 4) * 8)) * ROWB
                          + (((lane >> 3) & 1) * 8) * 2;

    const uint32_t a_off[3] = {SA_HI, SA_HI, SA_LO};
    const uint32_t b_off[3] = {SB_HI, SB_LO, SB_HI};

#pragma unroll
    for (int pass = 0; pass < 3; ++pass) {
        const uint32_t abase = sbase + a_off[pass] + a_lane;
        const uint32_t bbase = sbase + b_off[pass] + b_lane;
#pragma unroll
        for (int ks = 0; ks < 8; ++ks) {
            const uint32_t ko = ks * 32;
            uint32_t af[4][4];
#pragma unroll
            for (int mt = 0; mt < 4; ++mt)
                ldsm4(af[mt][0], af[mt][1], af[mt][2], af[mt][3],
                      abase + ko + (uint32_t)(mt * 16) * ROWB);
            uint32_t bf[4][2];
#pragma unroll
            for (int nt2 = 0; nt2 < 2; ++nt2) {
                uint32_t r0, r1, r2, r3;
                ldsm4(r0, r1, r2, r3, bbase + ko + (uint32_t)(nt2 * 16) * ROWB);
                bf[nt2 * 2 + 0][0] = r0; bf[nt2 * 2 + 0][1] = r1;
                bf[nt2 * 2 + 1][0] = r2; bf[nt2 * 2 + 1][1] = r3;
            }
#pragma unroll
            for (int mt = 0; mt < 4; ++mt)
#pragma unroll
                for (int nt = 0; nt < 4; ++nt)
                    mma16816(acc[mt][nt], af[mt], bf[nt]);
        }
    }

    const int rbase = row0 + wm * 64 + (lane >> 2);
    const int cbase = half * 128 + wn * 32 + 2 * (lane & 3);
#pragma unroll
    for (int mt = 0; mt < 4; ++mt) {
#pragma unroll
        for (int nt = 0; nt < 4; ++nt) {
            const int cg = cbase + nt * 8;
            const float b0 = bias[cg], b1 = bias[cg + 1];
            float v0 = acc[mt][nt][0] + b0;
            float v1 = acc[mt][nt][1] + b1;
            float v2 = acc[mt][nt][2] + b0;
            float v3 = acc[mt][nt][3] + b1;
            if (mtx == 2) {
                v0 = fmaxf(v0, 0.0f); v1 = fmaxf(v1, 0.0f);
                v2 = fmaxf(v2, 0.0f); v3 = fmaxf(v3, 0.0f);
            }
            const int rg = rbase + mt * 16;
            *(float2*)(outp + (size_t)rg * D_MODEL + cg)       = make_float2(v0, v1);
            *(float2*)(outp + (size_t)(rg + 8) * D_MODEL + cg) = make_float2(v2, v3);
        }
    }
}

// ---------------------------------------------------------------------------
// Tensor-core attention: one CTA per (b,h), SIX warps (2 m16 tiles each),
// flash-style streaming. Same smem layout as R11 (2 CTAs/SM), more warps/SM.
// ---------------------------------------------------------------------------
#define AQH 0
#define AQL (192 * 40)
#define AKH (2 * 192 * 40)
#define AKL (AKH + 176 * 40)
#define AVH (AKL + 176 * 40)
#define AVL (AVH + 32 * 184)
#define ASMEM_ELEMS (AVL + 32 * 184)
#define ASMEM_BYTES (ASMEM_ELEMS * 2)    // 82432 B

__global__ __launch_bounds__(192) void attn_mma_kernel(float* __restrict__ out)
{
    extern __shared__ char smemc[];
    __nv_bfloat16* sm = (__nv_bfloat16*)smemc;

    const int bh = blockIdx.x;
    const int b  = bh >> 3;
    const int h  = bh & 7;
    const int tid  = threadIdx.x;
    const int w    = tid >> 5;
    const int lane = tid & 31;

    // ---- stage q (scaled), k, v^T as bf16 hi/lo ----
    {
        const float* qg = g_q + ((size_t)b * SEQ) * D_MODEL + h * H_DIM;
        const float* kg = g_k + ((size_t)b * SEQ) * D_MODEL + h * H_DIM;
        const float* vg = g_v + ((size_t)b * SEQ) * D_MODEL + h * H_DIM;
        for (int idx = tid; idx < SEQ * 8; idx += 192) {
            const int t = idx >> 3, f = idx & 7;
            float4 q4 = *(const float4*)(qg + (size_t)t * D_MODEL + f * 4);
            q4.x *= SCALE; q4.y *= SCALE; q4.z *= SCALE; q4.w *= SCALE;
            {
                __nv_bfloat162 h0 = __floats2bfloat162_rn(q4.x, q4.y);
                __nv_bfloat162 h1 = __floats2bfloat162_rn(q4.z, q4.w);
                __nv_bfloat162 l0 = __floats2bfloat162_rn(q4.x - __bfloat162float(h0.x),
                                                          q4.y - __bfloat162float(h0.y));
                __nv_bfloat162 l1 = __floats2bfloat162_rn(q4.z - __bfloat162float(h1.x),
                                                          q4.w - __bfloat162float(h1.y));
                *(uint2*)(sm + AQH + t * 40 + f * 4) = make_uint2(*(uint32_t*)&h0, *(uint32_t*)&h1);
                *(uint2*)(sm + AQL + t * 40 + f * 4) = make_uint2(*(uint32_t*)&l0, *(uint32_t*)&l1);
            }
            float4 k4 = *(const float4*)(kg + (size_t)t * D_MODEL + f * 4);
            {
                __nv_bfloat162 h0 = __floats2bfloat162_rn(k4.x, k4.y);
                __nv_bfloat162 h1 = __floats2bfloat162_rn(k4.z, k4.w);
                __nv_bfloat162 l0 = __floats2bfloat162_rn(k4.x - __bfloat162float(h0.x),
                                                          k4.y - __bfloat162float(h0.y));
                __nv_bfloat162 l1 = __floats2bfloat162_rn(k4.z - __bfloat162float(h1.x),
                                                          k4.w - __bfloat162float(h1.y));
                *(uint2*)(sm + AKH + t * 40 + f * 4) = make_uint2(*(uint32_t*)&h0, *(uint32_t*)&h1);
                *(uint2*)(sm + AKL + t * 40 + f * 4) = make_uint2(*(uint32_t*)&l0, *(uint32_t*)&l1);
            }
            float4 v4 = *(const float4*)(vg + (size_t)t * D_MODEL + f * 4);
            float vv[4] = {v4.x, v4.y, v4.z, v4.w};
#pragma unroll
            for (int j = 0; j < 4; ++j) {
                const int d = f * 4 + j;
                __nv_bfloat16 hb = __float2bfloat16(vv[j]);
                sm[AVH + d * 184 + t] = hb;
                sm[AVL + d * 184 + t] = __float2bfloat16(vv[j] - __bfloat162float(hb));
            }
        }
        if (tid < 128) {
            const int t = 176 + (tid >> 3), f = tid & 7;
            *(uint2*)(sm + AQH + t * 40 + f * 4) = make_uint2(0u, 0u);
            *(uint2*)(sm + AQL + t * 40 + f * 4) = make_uint2(0u, 0u);
        }
    }
    __syncthreads();

    const uint32_t sb = smem_u32(sm);
    const uint32_t qh_b = sb + AQH * 2, ql_b = sb + AQL * 2;
    const uint32_t kh_b = sb + AKH * 2, kl_b = sb + AKL * 2;
    const uint32_t vh_b = sb + AVH * 2, vl_b = sb + AVL * 2;

    const uint32_t arow  = (uint32_t)(lane & 15);
    const uint32_t acolb = (uint32_t)((lane >> 4) * 16);
    const uint32_t brow  = (uint32_t)((lane & 7) + ((lane >> 4) * 8));
    const uint32_t bcolb = (uint32_t)(((lane >> 3) & 1) * 16);

    float accPV[2][4][4];
#pragma unroll
    for (int i = 0; i < 2; ++i)
#pragma unroll
        for (int j = 0; j < 4; ++j)
#pragma unroll
            for (int e = 0; e < 4; ++e) accPV[i][j][e] = 0.0f;
    float lsum[2][2] = {{0, 0}, {0, 0}};

    const int r_off = lane >> 2;
    const int c_off = 2 * (lane & 3);

    for (int tc = 0; tc < 11; ++tc) {
        const int t0 = tc * 16;

        uint32_t khf[2][4], klf[2][4];
#pragma unroll
        for (int d0 = 0; d0 < 2; ++d0) {
            const uint32_t off = (t0 + brow) * 80 + bcolb + d0 * 32;
            ldsm4(khf[d0][0], khf[d0][1], khf[d0][2], khf[d0][3], kh_b + off);
            ldsm4(klf[d0][0], klf[d0][1], klf[d0][2], klf[d0][3], kl_b + off);
        }
        uint32_t vhf[2][4], vlf[2][4];
#pragma unroll
        for (int dp = 0; dp < 2; ++dp) {
            const uint32_t off = (dp * 16 + brow) * 368 + (uint32_t)t0 * 2 + bcolb;
            ldsm4(vhf[dp][0], vhf[dp][1], vhf[dp][2], vhf[dp][3], vh_b + off);
            ldsm4(vlf[dp][0], vlf[dp][1], vlf[dp][2], vlf[dp][3], vl_b + off);
        }

        const int tA = t0 + c_off;
        const int tbA0 = tA / 22,       tbB0 = (tA + 1) / 22;
        const int tbA1 = (tA + 8) / 22, tbB1 = (tA + 9) / 22;

#pragma unroll
        for (int i = 0; i < 2; ++i) {
            const int m0 = (2 * w + i) * 16;
            float s[2][4];
#pragma unroll
            for (int nt = 0; nt < 2; ++nt)
#pragma unroll
                for (int e = 0; e < 4; ++e) s[nt][e] = 0.0f;

            uint32_t a[2][4];
            const uint32_t aoff = (m0 + arow) * 80 + acolb;
#pragma unroll
            for (int d0 = 0; d0 < 2; ++d0)
                ldsm4(a[d0][0], a[d0][1], a[d0][2], a[d0][3], qh_b + aoff + d0 * 32);
#pragma unroll
            for (int d0 = 0; d0 < 2; ++d0)
#pragma unroll
                for (int nt = 0; nt < 2; ++nt) {
                    mma16816(s[nt], a[d0], &khf[d0][nt * 2]);
                    mma16816(s[nt], a[d0], &klf[d0][nt * 2]);
                }
#pragma unroll
            for (int d0 = 0; d0 < 2; ++d0)
                ldsm4(a[d0][0], a[d0][1], a[d0][2], a[d0][3], ql_b + aoff + d0 * 32);
#pragma unroll
            for (int d0 = 0; d0 < 2; ++d0)
#pragma unroll
                for (int nt = 0; nt < 2; ++nt)
                    mma16816(s[nt], a[d0], &khf[d0][nt * 2]);

            // ---- mask + exp ----
            const int r0 = m0 + r_off;
            const int r1 = r0 + 8;
            const int rb0 = (r0 < SEQ) ? (r0 / 22) : -1;
            const int rb1 = (r1 < SEQ) ? (r1 / 22) : -1;

            float p[2][4];
#pragma unroll
            for (int nt = 0; nt < 2; ++nt) {
                const int tc0 = t0 + nt * 8 + c_off;
                const int tc1 = tc0 + 1;
                const int tb0 = nt ? tbA1 : tbA0;
                const int tb1 = nt ? tbB1 : tbB0;
                const float e0 = __expf(s[nt][0]);
                const float e1 = __expf(s[nt][1]);
                const float e2 = __expf(s[nt][2]);
                const float e3 = __expf(s[nt][3]);
                p[nt][0] = (rb0 == tb0 && r0 != tc0) ? 0.0f : e0;
                p[nt][1] = (rb0 == tb1 && r0 != tc1) ? 0.0f : e1;
                p[nt][2] = (rb1 == tb0 && r1 != tc0) ? 0.0f : e2;
                p[nt][3] = (rb1 == tb1 && r1 != tc1) ? 0.0f : e3;
            }
            lsum[i][0] += (p[0][0] + p[0][1]) + (p[1][0] + p[1][1]);
            lsum[i][1] += (p[0][2] + p[0][3]) + (p[1][2] + p[1][3]);

            // ---- repack S c-frag -> PV A-frag (hi/lo) ----
            uint32_t phi[4], plo[4];
#pragma unroll
            for (int nt = 0; nt < 2; ++nt)
#pragma unroll
                for (int hf = 0; hf < 2; ++hf) {
                    const float pa = p[nt][hf * 2], pb = p[nt][hf * 2 + 1];
                    __nv_bfloat162 hh = __floats2bfloat162_rn(pa, pb);
                    __nv_bfloat162 ll = __floats2bfloat162_rn(pa - __bfloat162float(hh.x),
                                                              pb - __bfloat162float(hh.y));
                    phi[nt * 2 + hf] = *(uint32_t*)&hh;
                    plo[nt * 2 + hf] = *(uint32_t*)&ll;
                }

            // ---- PV accumulate: 3 passes ----
#pragma unroll
            for (int dp = 0; dp < 2; ++dp)
#pragma unroll
                for (int nt = 0; nt < 2; ++nt) {
                    const int dt = dp * 2 + nt;
                    mma16816(accPV[i][dt], phi, &vhf[dp][nt * 2]);
                    mma16816(accPV[i][dt], plo, &vhf[dp][nt * 2]);
                    mma16816(accPV[i][dt], phi, &vlf[dp][nt * 2]);
                }
        }
    }

    // ---- reduce row sums across quad, normalize, store ----
#pragma unroll
    for (int i = 0; i < 2; ++i) {
#pragma unroll
        for (int j = 0; j < 2; ++j) {
            lsum[i][j] += __shfl_xor_sync(0xffffffffu, lsum[i][j], 1);
            lsum[i][j] += __shfl_xor_sync(0xffffffffu, lsum[i][j], 2);
        }
        const int m0 = (2 * w + i) * 16;
        const int r0 = m0 + r_off;
        const int r1 = r0 + 8;
        const float inv0 = 1.0f / lsum[i][0];
        const float inv1 = 1.0f / lsum[i][1];
        const int cb = h * H_DIM + c_off;
        if (r0 < SEQ) {
            float* o = out + ((size_t)b * SEQ + r0) * D_MODEL + cb;
#pragma unroll
            for (int dt = 0; dt < 4; ++dt)
                *(float2*)(o + dt * 8) = make_float2(accPV[i][dt][0] * inv0,
                                                     accPV[i][dt][1] * inv0);
        }
        if (r1 < SEQ) {
            float* o = out + ((size_t)b * SEQ + r1) * D_MODEL + cb;
#pragma unroll
            for (int dt = 0; dt < 4; ++dt)
                *(float2*)(o + dt * 8) = make_float2(accPV[i][dt][2] * inv1,
                                                     accPV[i][dt][3] * inv1);
        }
    }
}

// ---------------------------------------------------------------------------
extern "C" void kernel_launch(void* const* d_in, const int* in_sizes, int n_in,
                              void* d_out, int out_size)
{
    const float* x  = (const float*)d_in[0];
    const float* Wq = (const float*)d_in[1];
    const float* bq = (const float*)d_in[2];
    const float* Wk = (const float*)d_in[3];
    const float* bk = (const float*)d_in[4];
    const float* Wv = (const float*)d_in[5];
    const float* bv = (const float*)d_in[6];
    float* out = (float*)d_out;

    static int smem_set = 0;
    if (!smem_set) {
        cudaFuncSetAttribute(qkv_mma_kernel, cudaFuncAttributeMaxDynamicSharedMemorySize, SMTOT);
        cudaFuncSetAttribute(attn_mma_kernel, cudaFuncAttributeMaxDynamicSharedMemorySize, ASMEM_BYTES);
        smem_set = 1;
    }

    split_x_kernel<<<(M_TOTAL * D_IN) / (256 * 4), 256>>>(x);
    split_w_kernel<<<dim3(D_MODEL, 3), 128>>>(Wq, Wk, Wv);
    qkv_mma_kernel<<<dim3(M_TOTAL / 128, 6), 256, SMTOT>>>(bq, bk, bv);
    attn_mma_kernel<<<BATCH * H_NUM, 192, ASMEM_BYTES>>>(out);
}

// round 16
// speedup vs baseline: 1.2748x; 1.2748x over previous
#include <cuda_runtime.h>
#include <cuda_bf16.h>
#include <math.h>
#include <stdint.h>

// Problem constants
#define BATCH    256
#define SEQ      176
#define TIME_LEN 8
#define JOINTS   22
#define D_IN     128
#define H_NUM    8
#define H_DIM    32
#define D_MODEL  256
#define M_TOTAL  (BATCH * SEQ)   // 45056
#define SCALE    0.17677669529663687f

typedef unsigned long long u64;

// ---- warp MMA helpers (plain sm_80+ PTX; valid on sm_103 non-'a') ----
__device__ __forceinline__ uint32_t smem_u32(const void* p) {
    uint32_t a;
    asm("{ .reg .u64 t; cvta.to.shared.u64 t, %1; cvt.u32.u64 %0, t; }" : "=r"(a) : "l"(p));
    return a;
}
__device__ __forceinline__ void ldsm4(uint32_t& r0, uint32_t& r1, uint32_t& r2, uint32_t& r3,
                                      uint32_t addr) {
    asm volatile("ldmatrix.sync.aligned.m8n8.x4.shared.b16 {%0,%1,%2,%3}, [%4];"
                 : "=r"(r0), "=r"(r1), "=r"(r2), "=r"(r3) : "r"(addr));
}
__device__ __forceinline__ void mma16816(float* c, const uint32_t* a, const uint32_t* b) {
    asm volatile(
        "mma.sync.aligned.m16n8k16.row.col.f32.bf16.bf16.f32 "
        "{%0,%1,%2,%3}, {%4,%5,%6,%7}, {%8,%9}, {%0,%1,%2,%3};"
        : "+f"(c[0]), "+f"(c[1]), "+f"(c[2]), "+f"(c[3])
        : "r"(a[0]), "r"(a[1]), "r"(a[2]), "r"(a[3]), "r"(b[0]), "r"(b[1]));
}

// ---- device scratch ----
__device__ float g_q[(size_t)M_TOTAL * D_MODEL];
__device__ float g_k[(size_t)M_TOTAL * D_MODEL];
__device__ float g_v[(size_t)M_TOTAL * D_MODEL];
__device__ __nv_bfloat16 g_xhi[(size_t)M_TOTAL * D_IN];
__device__ __nv_bfloat16 g_xlo[(size_t)M_TOTAL * D_IN];
__device__ __nv_bfloat16 g_wthi[3 * D_MODEL * D_IN];   // transposed: [mtx][n][k]
__device__ __nv_bfloat16 g_wtlo[3 * D_MODEL * D_IN];

// ---------------------------------------------------------------------------
// Split kernels: fp32 -> bf16 hi/lo
// ---------------------------------------------------------------------------
__global__ __launch_bounds__(256) void split_x_kernel(const float* __restrict__ x)
{
    size_t i = ((size_t)blockIdx.x * 256 + threadIdx.x) * 4;
    float4 v = *(const float4*)(x + i);
    __nv_bfloat16 h0 = __float2bfloat16(v.x), h1 = __float2bfloat16(v.y);
    __nv_bfloat16 h2 = __float2bfloat16(v.z), h3 = __float2bfloat16(v.w);
    __nv_bfloat16 l0 = __float2bfloat16(v.x - __bfloat162float(h0));
    __nv_bfloat16 l1 = __float2bfloat16(v.y - __bfloat162float(h1));
    __nv_bfloat16 l2 = __float2bfloat16(v.z - __bfloat162float(h2));
    __nv_bfloat16 l3 = __float2bfloat16(v.w - __bfloat162float(h3));
    __nv_bfloat162 hA; hA.x = h0; hA.y = h1;
    __nv_bfloat162 hB; hB.x = h2; hB.y = h3;
    __nv_bfloat162 lA; lA.x = l0; lA.y = l1;
    __nv_bfloat162 lB; lB.x = l2; lB.y = l3;
    *(__nv_bfloat162*)(g_xhi + i)     = hA;
    *(__nv_bfloat162*)(g_xhi + i + 2) = hB;
    *(__nv_bfloat162*)(g_xlo + i)     = lA;
    *(__nv_bfloat162*)(g_xlo + i + 2) = lB;
}

// W [k=128][n=256] row-major -> Wt [n=256][k=128], split hi/lo. grid (256,3) x 128
__global__ __launch_bounds__(128) void split_w_kernel(
    const float* __restrict__ Wq, const float* __restrict__ Wk, const float* __restrict__ Wv)
{
    const int n = blockIdx.x;
    const int m = blockIdx.y;
    const int k = threadIdx.x;
    const float* W = (m == 0) ? Wq : (m == 1) ? Wk : Wv;
    float v = W[(size_t)k * D_MODEL + n];
    __nv_bfloat16 h = __float2bfloat16(v);
    __nv_bfloat16 l = __float2bfloat16(v - __bfloat162float(h));
    size_t o = (size_t)m * D_MODEL * D_IN + (size_t)n * D_IN + k;
    g_wthi[o] = h;
    g_wtlo[o] = l;
}

// ---------------------------------------------------------------------------
// QKV projection via warp-level mma.sync (bf16, 2-way split, 3 passes).
// Per CTA: M=128 x N=128 x K=128 fully smem-resident. grid=(352, 6).
// (R10/R11 configuration — best measured.)
// ---------------------------------------------------------------------------
#define ROWB 272                    // bytes per smem row (128 bf16 + 8 pad)
#define SA_HI 0
#define SA_LO (128 * ROWB)
#define SB_HI (2 * 128 * ROWB)
#define SB_LO (3 * 128 * ROWB)
#define SMTOT (4 * 128 * ROWB)      // 139264 B

__global__ __launch_bounds__(256) void qkv_mma_kernel(
    const float* __restrict__ bq, const float* __restrict__ bk, const float* __restrict__ bv)
{
    extern __shared__ char smem[];
    const uint32_t sbase = smem_u32(smem);
    const int tid  = threadIdx.x;
    const int w    = tid >> 5;
    const int lane = tid & 31;
    const int mtx  = blockIdx.y >> 1;
    const int half = blockIdx.y & 1;
    const int row0 = blockIdx.x * 128;

    const float* bias = (mtx == 0) ? bq : (mtx == 1) ? bk : bv;
    float* outp       = (mtx == 0) ? g_q : (mtx == 1) ? g_k : g_v;
    const __nv_bfloat16* wth = g_wthi + (size_t)mtx * D_MODEL * D_IN + (size_t)half * 128 * D_IN;
    const __nv_bfloat16* wtl = g_wtlo + (size_t)mtx * D_MODEL * D_IN + (size_t)half * 128 * D_IN;

    for (int idx = tid; idx < 2048; idx += 256) {
        const int r = idx >> 4;
        const int c = (idx & 15) * 8;
        const uint32_t doff = (uint32_t)r * ROWB + c * 2;
        *(uint4*)(smem + SA_HI + doff) = *(const uint4*)(g_xhi + (size_t)(row0 + r) * D_IN + c);
        *(uint4*)(smem + SA_LO + doff) = *(const uint4*)(g_xlo + (size_t)(row0 + r) * D_IN + c);
        *(uint4*)(smem + SB_HI + doff) = *(const uint4*)(wth + (size_t)r * D_IN + c);
        *(uint4*)(smem + SB_LO + doff) = *(const uint4*)(wtl + (size_t)r * D_IN + c);
    }
    __syncthreads();

    const int wm = w & 1;
    const int wn = w >> 1;

    float acc[4][4][4];
#pragma unroll
    for (int i = 0; i < 4; ++i)
#pragma unroll
        for (int j = 0; j < 4; ++j)
#pragma unroll
            for (int e = 0; e < 4; ++e) acc[i][j][e] = 0.0f;

    const uint32_t a_lane = (uint32_t)(wm * 64 + (lane & 15)) * ROWB + ((lane >> 4) * 8) * 2;
    const uint32_t b_lane = (uint32_t)(wn * 32 + (lane & 7) + ((lane >> 4) * 8)) * ROWB
                          + (((lane >> 3) & 1) * 8) * 2;

    const uint32_t a_off[3] = {SA_HI, SA_HI, SA_LO};
    const uint32_t b_off[3] = {SB_HI, SB_LO, SB_HI};

#pragma unroll
    for (int pass = 0; pass < 3; ++pass) {
        const uint32_t abase = sbase + a_off[pass] + a_lane;
        const uint32_t bbase = sbase + b_off[pass] + b_lane;
#pragma unroll
        for (int ks = 0; ks < 8; ++ks) {
            const uint32_t ko = ks * 32;
            uint32_t af[4][4];
#pragma unroll
            for (int mt = 0; mt < 4; ++mt)
                ldsm4(af[mt][0], af[mt][1], af[mt][2], af[mt][3],
                      abase + ko + (uint32_t)(mt * 16) * ROWB);
            uint32_t bf[4][2];
#pragma unroll
            for (int nt2 = 0; nt2 < 2; ++nt2) {
                uint32_t r0, r1, r2, r3;
                ldsm4(r0, r1, r2, r3, bbase + ko + (uint32_t)(nt2 * 16) * ROWB);
                bf[nt2 * 2 + 0][0] = r0; bf[nt2 * 2 + 0][1] = r1;
                bf[nt2 * 2 + 1][0] = r2; bf[nt2 * 2 + 1][1] = r3;
            }
#pragma unroll
            for (int mt = 0; mt < 4; ++mt)
#pragma unroll
                for (int nt = 0; nt < 4; ++nt)
                    mma16816(acc[mt][nt], af[mt], bf[nt]);
        }
    }

    const int rbase = row0 + wm * 64 + (lane >> 2);
    const int cbase = half * 128 + wn * 32 + 2 * (lane & 3);
#pragma unroll
    for (int mt = 0; mt < 4; ++mt) {
#pragma unroll
        for (int nt = 0; nt < 4; ++nt) {
            const int cg = cbase + nt * 8;
            const float b0 = bias[cg], b1 = bias[cg + 1];
            float v0 = acc[mt][nt][0] + b0;
            float v1 = acc[mt][nt][1] + b1;
            float v2 = acc[mt][nt][2] + b0;
            float v3 = acc[mt][nt][3] + b1;
            if (mtx == 2) {
                v0 = fmaxf(v0, 0.0f); v1 = fmaxf(v1, 0.0f);
                v2 = fmaxf(v2, 0.0f); v3 = fmaxf(v3, 0.0f);
            }
            const int rg = rbase + mt * 16;
            *(float2*)(outp + (size_t)rg * D_MODEL + cg)       = make_float2(v0, v1);
            *(float2*)(outp + (size_t)(rg + 8) * D_MODEL + cg) = make_float2(v2, v3);
        }
    }
}

// ---------------------------------------------------------------------------
// Tensor-core attention (R11 config): one CTA per (b,h), 4 warps, 3 m16 tiles
// each — but tile 11 (rows 176-191) is pure padding and is SKIPPED entirely
// (warp 3 computes only 2 real tiles). 2 CTAs/SM.
// ---------------------------------------------------------------------------
#define AQH 0
#define AQL (192 * 40)
#define AKH (2 * 192 * 40)
#define AKL (AKH + 176 * 40)
#define AVH (AKL + 176 * 40)
#define AVL (AVH + 32 * 184)
#define ASMEM_ELEMS (AVL + 32 * 184)
#define ASMEM_BYTES (ASMEM_ELEMS * 2)    // 82432 B

__global__ __launch_bounds__(128) void attn_mma_kernel(float* __restrict__ out)
{
    extern __shared__ char smemc[];
    __nv_bfloat16* sm = (__nv_bfloat16*)smemc;

    const int bh = blockIdx.x;
    const int b  = bh >> 3;
    const int h  = bh & 7;
    const int tid  = threadIdx.x;
    const int w    = tid >> 5;
    const int lane = tid & 31;

    // ---- stage q (scaled), k, v^T as bf16 hi/lo ----
    {
        const float* qg = g_q + ((size_t)b * SEQ) * D_MODEL + h * H_DIM;
        const float* kg = g_k + ((size_t)b * SEQ) * D_MODEL + h * H_DIM;
        const float* vg = g_v + ((size_t)b * SEQ) * D_MODEL + h * H_DIM;
        for (int idx = tid; idx < SEQ * 8; idx += 128) {
            const int t = idx >> 3, f = idx & 7;
            float4 q4 = *(const float4*)(qg + (size_t)t * D_MODEL + f * 4);
            q4.x *= SCALE; q4.y *= SCALE; q4.z *= SCALE; q4.w *= SCALE;
            {
                __nv_bfloat162 h0 = __floats2bfloat162_rn(q4.x, q4.y);
                __nv_bfloat162 h1 = __floats2bfloat162_rn(q4.z, q4.w);
                __nv_bfloat162 l0 = __floats2bfloat162_rn(q4.x - __bfloat162float(h0.x),
                                                          q4.y - __bfloat162float(h0.y));
                __nv_bfloat162 l1 = __floats2bfloat162_rn(q4.z - __bfloat162float(h1.x),
                                                          q4.w - __bfloat162float(h1.y));
                *(uint2*)(sm + AQH + t * 40 + f * 4) = make_uint2(*(uint32_t*)&h0, *(uint32_t*)&h1);
                *(uint2*)(sm + AQL + t * 40 + f * 4) = make_uint2(*(uint32_t*)&l0, *(uint32_t*)&l1);
            }
            float4 k4 = *(const float4*)(kg + (size_t)t * D_MODEL + f * 4);
            {
                __nv_bfloat162 h0 = __floats2bfloat162_rn(k4.x, k4.y);
                __nv_bfloat162 h1 = __floats2bfloat162_rn(k4.z, k4.w);
                __nv_bfloat162 l0 = __floats2bfloat162_rn(k4.x - __bfloat162float(h0.x),
                                                          k4.y - __bfloat162float(h0.y));
                __nv_bfloat162 l1 = __floats2bfloat162_rn(k4.z - __bfloat162float(h1.x),
                                                          k4.w - __bfloat162float(h1.y));
                *(uint2*)(sm + AKH + t * 40 + f * 4) = make_uint2(*(uint32_t*)&h0, *(uint32_t*)&h1);
                *(uint2*)(sm + AKL + t * 40 + f * 4) = make_uint2(*(uint32_t*)&l0, *(uint32_t*)&l1);
            }
            float4 v4 = *(const float4*)(vg + (size_t)t * D_MODEL + f * 4);
            float vv[4] = {v4.x, v4.y, v4.z, v4.w};
#pragma unroll
            for (int j = 0; j < 4; ++j) {
                const int d = f * 4 + j;
                __nv_bfloat16 hb = __float2bfloat16(vv[j]);
                sm[AVH + d * 184 + t] = hb;
                sm[AVL + d * 184 + t] = __float2bfloat16(vv[j] - __bfloat162float(hb));
            }
        }
    }
    __syncthreads();

    const uint32_t sb = smem_u32(sm);
    const uint32_t qh_b = sb + AQH * 2, ql_b = sb + AQL * 2;
    const uint32_t kh_b = sb + AKH * 2, kl_b = sb + AKL * 2;
    const uint32_t vh_b = sb + AVH * 2, vl_b = sb + AVL * 2;

    const uint32_t arow  = (uint32_t)(lane & 15);
    const uint32_t acolb = (uint32_t)((lane >> 4) * 16);
    const uint32_t brow  = (uint32_t)((lane & 7) + ((lane >> 4) * 8));
    const uint32_t bcolb = (uint32_t)(((lane >> 3) & 1) * 16);

    float accPV[3][4][4];
#pragma unroll
    for (int i = 0; i < 3; ++i)
#pragma unroll
        for (int j = 0; j < 4; ++j)
#pragma unroll
            for (int e = 0; e < 4; ++e) accPV[i][j][e] = 0.0f;
    float lsum[3][2] = {{0, 0}, {0, 0}, {0, 0}};

    const int r_off = lane >> 2;
    const int c_off = 2 * (lane & 3);
    const int ntiles = (w == 3) ? 2 : 3;     // tile 11 is all padding — skip

    for (int tc = 0; tc < 11; ++tc) {
        const int t0 = tc * 16;

        uint32_t khf[2][4], klf[2][4];
#pragma unroll
        for (int d0 = 0; d0 < 2; ++d0) {
            const uint32_t off = (t0 + brow) * 80 + bcolb + d0 * 32;
            ldsm4(khf[d0][0], khf[d0][1], khf[d0][2], khf[d0][3], kh_b + off);
            ldsm4(klf[d0][0], klf[d0][1], klf[d0][2], klf[d0][3], kl_b + off);
        }
        uint32_t vhf[2][4], vlf[2][4];
#pragma unroll
        for (int dp = 0; dp < 2; ++dp) {
            const uint32_t off = (dp * 16 + brow) * 368 + (uint32_t)t0 * 2 + bcolb;
            ldsm4(vhf[dp][0], vhf[dp][1], vhf[dp][2], vhf[dp][3], vh_b + off);
            ldsm4(vlf[dp][0], vlf[dp][1], vlf[dp][2], vlf[dp][3], vl_b + off);
        }

        const int tA = t0 + c_off;
        const int tbA0 = tA / 22,       tbB0 = (tA + 1) / 22;
        const int tbA1 = (tA + 8) / 22, tbB1 = (tA + 9) / 22;

#pragma unroll
        for (int i = 0; i < 3; ++i) {
            if (i >= ntiles) break;          // uniform per-warp
            const int m0 = (3 * w + i) * 16;
            float s[2][4];
#pragma unroll
            for (int nt = 0; nt < 2; ++nt)
#pragma unroll
                for (int e = 0; e < 4; ++e) s[nt][e] = 0.0f;

            uint32_t a[2][4];
            const uint32_t aoff = (m0 + arow) * 80 + acolb;
#pragma unroll
            for (int d0 = 0; d0 < 2; ++d0)
                ldsm4(a[d0][0], a[d0][1], a[d0][2], a[d0][3], qh_b + aoff + d0 * 32);
#pragma unroll
            for (int d0 = 0; d0 < 2; ++d0)
#pragma unroll
                for (int nt = 0; nt < 2; ++nt) {
                    mma16816(s[nt], a[d0], &khf[d0][nt * 2]);
                    mma16816(s[nt], a[d0], &klf[d0][nt * 2]);
                }
#pragma unroll
            for (int d0 = 0; d0 < 2; ++d0)
                ldsm4(a[d0][0], a[d0][1], a[d0][2], a[d0][3], ql_b + aoff + d0 * 32);
#pragma unroll
            for (int d0 = 0; d0 < 2; ++d0)
#pragma unroll
                for (int nt = 0; nt < 2; ++nt)
                    mma16816(s[nt], a[d0], &khf[d0][nt * 2]);

            // ---- mask + exp ----
            const int r0 = m0 + r_off;
            const int r1 = r0 + 8;
            const int rb0 = r0 / 22;
            const int rb1 = r1 / 22;

            float p[2][4];
#pragma unroll
            for (int nt = 0; nt < 2; ++nt) {
                const int tc0 = t0 + nt * 8 + c_off;
                const int tc1 = tc0 + 1;
                const int tb0 = nt ? tbA1 : tbA0;
                const int tb1 = nt ? tbB1 : tbB0;
                const float e0 = __expf(s[nt][0]);
                const float e1 = __expf(s[nt][1]);
                const float e2 = __expf(s[nt][2]);
                const float e3 = __expf(s[nt][3]);
                p[nt][0] = (rb0 == tb0 && r0 != tc0) ? 0.0f : e0;
                p[nt][1] = (rb0 == tb1 && r0 != tc1) ? 0.0f : e1;
                p[nt][2] = (rb1 == tb0 && r1 != tc0) ? 0.0f : e2;
                p[nt][3] = (rb1 == tb1 && r1 != tc1) ? 0.0f : e3;
            }
            lsum[i][0] += (p[0][0] + p[0][1]) + (p[1][0] + p[1][1]);
            lsum[i][1] += (p[0][2] + p[0][3]) + (p[1][2] + p[1][3]);

            // ---- repack S c-frag -> PV A-frag (hi/lo) ----
            uint32_t phi[4], plo[4];
#pragma unroll
            for (int nt = 0; nt < 2; ++nt)
#pragma unroll
                for (int hf = 0; hf < 2; ++hf) {
                    const float pa = p[nt][hf * 2], pb = p[nt][hf * 2 + 1];
                    __nv_bfloat162 hh = __floats2bfloat162_rn(pa, pb);
                    __nv_bfloat162 ll = __floats2bfloat162_rn(pa - __bfloat162float(hh.x),
                                                              pb - __bfloat162float(hh.y));
                    phi[nt * 2 + hf] = *(uint32_t*)&hh;
                    plo[nt * 2 + hf] = *(uint32_t*)&ll;
                }

            // ---- PV accumulate: 3 passes ----
#pragma unroll
            for (int dp = 0; dp < 2; ++dp)
#pragma unroll
                for (int nt = 0; nt < 2; ++nt) {
                    const int dt = dp * 2 + nt;
                    mma16816(accPV[i][dt], phi, &vhf[dp][nt * 2]);
                    mma16816(accPV[i][dt], plo, &vhf[dp][nt * 2]);
                    mma16816(accPV[i][dt], phi, &vlf[dp][nt * 2]);
                }
        }
    }

    // ---- reduce row sums across quad, normalize, store ----
#pragma unroll
    for (int i = 0; i < 3; ++i) {
        if (i >= ntiles) break;              // uniform per-warp
#pragma unroll
        for (int j = 0; j < 2; ++j) {
            lsum[i][j] += __shfl_xor_sync(0xffffffffu, lsum[i][j], 1);
            lsum[i][j] += __shfl_xor_sync(0xffffffffu, lsum[i][j], 2);
        }
        const int m0 = (3 * w + i) * 16;
        const int r0 = m0 + r_off;
        const int r1 = r0 + 8;
        const float inv0 = 1.0f / lsum[i][0];
        const float inv1 = 1.0f / lsum[i][1];
        const int cb = h * H_DIM + c_off;
        {
            float* o = out + ((size_t)b * SEQ + r0) * D_MODEL + cb;
#pragma unroll
            for (int dt = 0; dt < 4; ++dt)
                *(float2*)(o + dt * 8) = make_float2(accPV[i][dt][0] * inv0,
                                                     accPV[i][dt][1] * inv0);
        }
        {
            float* o = out + ((size_t)b * SEQ + r1) * D_MODEL + cb;
#pragma unroll
            for (int dt = 0; dt < 4; ++dt)
                *(float2*)(o + dt * 8) = make_float2(accPV[i][dt][2] * inv1,
                                                     accPV[i][dt][3] * inv1);
        }
    }
}

// ---------------------------------------------------------------------------
extern "C" void kernel_launch(void* const* d_in, const int* in_sizes, int n_in,
                              void* d_out, int out_size)
{
    const float* x  = (const float*)d_in[0];
    const float* Wq = (const float*)d_in[1];
    const float* bq = (const float*)d_in[2];
    const float* Wk = (const float*)d_in[3];
    const float* bk = (const float*)d_in[4];
    const float* Wv = (const float*)d_in[5];
    const float* bv = (const float*)d_in[6];
    float* out = (float*)d_out;

    static int smem_set = 0;
    if (!smem_set) {
        cudaFuncSetAttribute(qkv_mma_kernel, cudaFuncAttributeMaxDynamicSharedMemorySize, SMTOT);
        cudaFuncSetAttribute(attn_mma_kernel, cudaFuncAttributeMaxDynamicSharedMemorySize, ASMEM_BYTES);
        smem_set = 1;
    }

    split_x_kernel<<<(M_TOTAL * D_IN) / (256 * 4), 256>>>(x);
    split_w_kernel<<<dim3(D_MODEL, 3), 128>>>(Wq, Wk, Wv);
    qkv_mma_kernel<<<dim3(M_TOTAL / 128, 6), 256, SMTOT>>>(bq, bk, bv);
    attn_mma_kernel<<<BATCH * H_NUM, 128, ASMEM_BYTES>>>(out);
}